// round 11
// baseline (speedup 1.0000x reference)
#include <cuda_runtime.h>
#include <cstdint>

// ButterflyRotationLayer: R = B(d,d) @ B(d,d/2) @ ... @ B(d,2), d=4096, 12 stages.
//
// Split at k=64:
//   H = stages k=4096..128 : H[r,l] != 0 only when l == r (mod 64).
//       For fixed r6 = r&63, the 64 rows {r6+64*rh} share ONE 64x64 m-space
//       butterfly matrix Hhat_{r6}[rh, m].
//   T = stages k=64..2     : block-diagonal, 64 independent 64x64 matrices That_B.
// Exactly one l contributes per output element:
//   R[r6+64*rh, 64*B+cc] = Hhat_{r6}[rh, B] * That_B[r6, cc]
//
// FUSED single launch (v2). v1 (round 8) lost because merging pushed regs to
// 40 -> 6 blocks/SM instead of 8 -> outer phase went 1.7 -> 2.3 waves.
// Fix: __launch_bounds__(256, 8) pins regs <= 32 (spills, if any, hit only the
// 128 mats blocks, off the critical byte path). Blocks 0..127 (wave-1 resident
// by construction) build the matrices and bump g_ready; everyone else polls
// cheaply, then all 2048 blocks run the store-bound outer role with plain
// STG.128 (measured best). Last block resets counters -> identical work/call.

#define D 4096

// g_H[r*64 + m]  = Hhat_{r&63}[r>>6, m]
__device__ __align__(16) float g_H[D * 64];
// g_T[(B*64+rr)*64 + cc] = That_B[rr, cc]
__device__ __align__(16) float g_T[D * 64];

__device__ unsigned g_ready;   // zero-init at load; reset by last block each launch
__device__ unsigned g_exit;

__global__ __launch_bounds__(256, 8) void butterfly_fused_kernel(
    const float* __restrict__ thetas, float4* __restrict__ out) {

    __shared__ float sm[64][65];
    __shared__ float cs_c[6][32], cs_s[6][32];

    const int tid = threadIdx.x;
    const int bid = blockIdx.x;

    // =====================================================================
    // Role 1 (blocks 0..127): build matrix bid (head if <64 else tail).
    // M = I; stages apply column Givens rotations (M <- M @ B_i).
    // All 192 (c,s) pairs computed in parallel upfront.
    // =====================================================================
    if (bid < 128) {
        const bool is_head = (bid < 64);

        if (tid < 192) {
            const int ii   = tid >> 5;
            const int j    = tid & 31;
            const int half = 32 >> ii;
            const int bm   = j >> (5 - ii);
            const int jm   = j & (half - 1);
            const int p_loc = (bm << (6 - ii)) + jm;
            int theta_idx;
            if (is_head) {
                const int p    = bid + (p_loc << 6);
                const int logk = 12 - ii;
                const int hh   = 2048 >> ii;
                theta_idx = ii * 2048 + (p >> logk) * hh + (p & ((1 << logk) - 1));
            } else {
                const int p    = ((bid - 64) << 6) + p_loc;
                const int logk = 6 - ii;
                const int hh   = 32 >> ii;
                theta_idx = (ii + 6) * 2048 + (p >> logk) * hh + (p & ((1 << logk) - 1));
            }
            float s, c;
            sincosf(thetas[theta_idx], &s, &c);
            cs_c[ii][j] = c;
            cs_s[ii][j] = s;
        }

#pragma unroll
        for (int k = 0; k < 16; ++k) {
            const int e = tid + k * 256;
            sm[e >> 6][e & 63] = ((e >> 6) == (e & 63)) ? 1.0f : 0.0f;
        }
        __syncthreads();

        const int j = tid & 31;
#pragma unroll
        for (int ii = 0; ii < 6; ++ii) {
            const int half  = 32 >> ii;
            const int bm    = j >> (5 - ii);
            const int jm    = j & (half - 1);
            const int p_loc = (bm << (6 - ii)) + jm;
            const int q_loc = p_loc + half;
            const float c = cs_c[ii][j];
            const float s = cs_s[ii][j];
#pragma unroll
            for (int k = 0; k < 8; ++k) {
                const int row = (tid >> 5) + (k << 3);
                const float a  = sm[row][p_loc];
                const float bb = sm[row][q_loc];
                sm[row][p_loc] = c * a + s * bb;
                sm[row][q_loc] = c * bb - s * a;
            }
            __syncthreads();
        }

        if (is_head) {
#pragma unroll
            for (int k = 0; k < 16; ++k) {
                const int e  = tid + k * 256;
                const int rh = e >> 6;
                const int m  = e & 63;
                g_H[(bid << 6) + (rh << 12) + m] = sm[rh][m];
            }
        } else {
            const int base = (bid - 64) << 12;
#pragma unroll
            for (int k = 0; k < 16; ++k) {
                const int e = tid + k * 256;
                g_T[base + e] = sm[e >> 6][e & 63];
            }
        }

        __threadfence();          // release: matrix stores before the signal
        __syncthreads();
        if (tid == 0) atomicAdd(&g_ready, 1u);
    }

    // =====================================================================
    // Barrier: wait until all 128 matrices are published.
    // =====================================================================
    if (tid == 0) {
        while (*(volatile unsigned*)&g_ready < 128u) __nanosleep(32);
        __threadfence();          // acquire
    }
    __syncthreads();

    // =====================================================================
    // Role 2 (all 2048 blocks): outer-product tile. Thread loads its t-float4
    // once, emits 8 output rows (stride 64) with plain coalesced STG.128.
    // =====================================================================
    {
        const int ch  = bid & 3;                    // column chunk
        const int r6  = (bid >> 2) & 63;
        const int g   = bid >> 8;                   // 0..7
        const int c4  = (ch << 8) | tid;            // float4 index within row
        const int c   = c4 << 2;
        const int B   = c >> 6;

        const int l = (B << 6) + r6;
        const float4 t = *reinterpret_cast<const float4*>(&g_T[(l << 6) + (c & 63)]);

        const int r0 = r6 + (g << 9);               // rows r0 + 64*jr
        const float* __restrict__ hp = &g_H[(r0 << 6) + B];
        float h[8];
#pragma unroll
        for (int jr = 0; jr < 8; ++jr)
            h[jr] = hp[jr << 12];                   // +64 rows * 64 floats each

        float4* __restrict__ o = out + (((long)r0 << 10) + c4);
#pragma unroll
        for (int jr = 0; jr < 8; ++jr) {
            const float hh = h[jr];
            o[(long)jr << 16] = make_float4(hh * t.x, hh * t.y, hh * t.z, hh * t.w);
        }
    }

    // =====================================================================
    // Last block out resets counters so every launch does identical work.
    // =====================================================================
    if (tid == 0) {
        __threadfence();
        const unsigned n = atomicAdd(&g_exit, 1u);
        if (n == 2047u) {
            g_ready = 0u;
            g_exit  = 0u;
            __threadfence();
        }
    }
}

extern "C" void kernel_launch(void* const* d_in, const int* in_sizes, int n_in,
                              void* d_out, int out_size) {
    const float* thetas = (const float*)d_in[0];  // [12, 2048] fp32
    float4* out = (float4*)d_out;                 // [4096, 4096] fp32

    butterfly_fused_kernel<<<2048, 256>>>(thetas, out);
}

// round 12
// speedup vs baseline: 1.3328x; 1.3328x over previous
#include <cuda_runtime.h>
#include <cstdint>

// ButterflyRotationLayer: R = B(d,d) @ B(d,d/2) @ ... @ B(d,2), d=4096, 12 stages.
//
// Split at k=64:
//   H = stages k=4096..128 : H[r,l] != 0 only when l == r (mod 64).
//       For fixed r6 = r&63, the 64 rows {r6+64*rh} share ONE 64x64 m-space
//       butterfly matrix Hhat_{r6}[rh, m].
//   T = stages k=64..2     : block-diagonal, 64 independent 64x64 matrices That_B.
// Exactly one l contributes per output element:
//   R[r6+64*rh, 64*B+cc] = Hhat_{r6}[rh, B] * That_B[r6, cc]
//
// Two kernels + PDL (fused/spin variants measured +5us twice; __stcs +1us).
//   K1 (256 blocks): each block builds HALF of one 64x64 matrix (32 rows) ->
//      halves the per-stage serial work vs 128-block version. Ends with
//      launch_dependents (PDL trigger).
//   K2 (2048 blocks, ProgrammaticStreamSerialization): waits via
//      griddepcontrol.wait after producer-independent index math; plain
//      STG.128 stores (measured best; ~13us L2-store-ceiling floor).

#define D 4096

// g_H[r*64 + m]  = Hhat_{r&63}[r>>6, m]
__device__ __align__(16) float g_H[D * 64];
// g_T[(B*64+rr)*64 + cc] = That_B[rr, cc]
__device__ __align__(16) float g_T[D * 64];

// ---------------------------------------------------------------------------
// Kernel 1: 256 blocks. Block b -> matrix mat=b>>1 (head if mat<64, else tail
// mat-64), row half hf=b&1 (rows hf*32..hf*32+31). M = I restricted to those
// rows; each stage applies column Givens rotations. All 192 (c,s) pairs
// computed in parallel upfront (theta indices depend only on mat).
// ---------------------------------------------------------------------------
__global__ __launch_bounds__(256) void butterfly_mats_kernel(const float* __restrict__ thetas) {
    __shared__ float sm[32][65];
    __shared__ float cs_c[6][32], cs_s[6][32];

    const int tid = threadIdx.x;
    const int b   = blockIdx.x;
    const int mat = b >> 1;
    const int hf  = b & 1;
    const bool is_head = (mat < 64);

    if (tid < 192) {
        const int ii   = tid >> 5;
        const int j    = tid & 31;
        const int half = 32 >> ii;
        const int bm   = j >> (5 - ii);
        const int jm   = j & (half - 1);
        const int p_loc = (bm << (6 - ii)) + jm;
        int theta_idx;
        if (is_head) {
            const int p    = mat + (p_loc << 6);
            const int logk = 12 - ii;
            const int hh   = 2048 >> ii;
            theta_idx = ii * 2048 + (p >> logk) * hh + (p & ((1 << logk) - 1));
        } else {
            const int p    = ((mat - 64) << 6) + p_loc;
            const int logk = 6 - ii;
            const int hh   = 32 >> ii;
            theta_idx = (ii + 6) * 2048 + (p >> logk) * hh + (p & ((1 << logk) - 1));
        }
        float s, c;
        sincosf(thetas[theta_idx], &s, &c);
        cs_c[ii][j] = c;
        cs_s[ii][j] = s;
    }

    // identity restricted to rows [hf*32, hf*32+32)
#pragma unroll
    for (int k = 0; k < 8; ++k) {
        const int e  = tid + k * 256;            // 0..2047
        const int lr = e >> 6;                   // local row 0..31
        const int m  = e & 63;
        sm[lr][m] = (((hf << 5) + lr) == m) ? 1.0f : 0.0f;
    }
    __syncthreads();

    const int j = tid & 31;

#pragma unroll
    for (int ii = 0; ii < 6; ++ii) {
        const int half  = 32 >> ii;
        const int bm    = j >> (5 - ii);
        const int jm    = j & (half - 1);
        const int p_loc = (bm << (6 - ii)) + jm;
        const int q_loc = p_loc + half;
        const float c = cs_c[ii][j];
        const float s = cs_s[ii][j];
#pragma unroll
        for (int k = 0; k < 4; ++k) {
            const int lr = (tid >> 5) + (k << 3);   // local row 0..31
            const float a  = sm[lr][p_loc];
            const float bb = sm[lr][q_loc];
            sm[lr][p_loc] = c * a + s * bb;
            sm[lr][q_loc] = c * bb - s * a;
        }
        __syncthreads();
    }

    if (is_head) {
        // g_H[(r6 + 64*rh)*64 + m] = Hhat_{r6=mat}[rh, m], rh = hf*32 + lr
#pragma unroll
        for (int k = 0; k < 8; ++k) {
            const int e  = tid + k * 256;
            const int lr = e >> 6;
            const int m  = e & 63;
            const int rh = (hf << 5) + lr;
            g_H[(mat << 6) + (rh << 12) + m] = sm[lr][m];
        }
    } else {
        // g_T[((mat-64)*64 + rr)*64 + cc], rr = hf*32 + lr
        const int base = ((mat - 64) << 12) + (hf << 11);
#pragma unroll
        for (int k = 0; k < 8; ++k) {
            const int e = tid + k * 256;
            g_T[base + e] = sm[e >> 6][e & 63];
        }
    }

    // PDL trigger: stores visible, then allow dependent grid to launch.
    __threadfence();
    asm volatile("griddepcontrol.launch_dependents;" ::: "memory");
}

// ---------------------------------------------------------------------------
// Kernel 2: thread (r6, g, c4) loads t = That_B[r6, c&63] once, then writes
// rows r = r6 + 64*(8g + jr):  R[r, c..c+3] = g_H[r*64 + B] * t.
// griddepcontrol.wait after producer-independent index math; plain STG.128.
// ---------------------------------------------------------------------------
__global__ __launch_bounds__(256) void outer_product_kernel(float4* __restrict__ out) {
    const int b   = blockIdx.x;                       // 0..2047
    const int c4  = ((b & 3) << 8) | threadIdx.x;     // 0..1023 (float4 within row)
    const int r6  = (b >> 2) & 63;
    const int g   = b >> 8;                           // 0..7
    const int c   = c4 << 2;
    const int B   = c >> 6;

    asm volatile("griddepcontrol.wait;" ::: "memory");

    const int l = (B << 6) + r6;
    const float4 t = *reinterpret_cast<const float4*>(&g_T[(l << 6) + (c & 63)]);

    const int r0 = r6 + (g << 9);                     // rows r0 + 64*jr
    const float* __restrict__ hp = &g_H[(r0 << 6) + B];
    float h[8];
#pragma unroll
    for (int jr = 0; jr < 8; ++jr)
        h[jr] = hp[jr << 12];                         // +jr*4096 floats (16 KB)

    float4* __restrict__ o = out + (((long)r0 << 10) + c4);
#pragma unroll
    for (int jr = 0; jr < 8; ++jr) {
        const float hh = h[jr];
        o[(long)jr << 16] = make_float4(hh * t.x, hh * t.y, hh * t.z, hh * t.w);
    }
}

extern "C" void kernel_launch(void* const* d_in, const int* in_sizes, int n_in,
                              void* d_out, int out_size) {
    const float* thetas = (const float*)d_in[0];  // [12, 2048] fp32
    float4* out = (float4*)d_out;                 // [4096, 4096] fp32

    butterfly_mats_kernel<<<256, 256>>>(thetas);

    cudaLaunchConfig_t cfg = {};
    cfg.gridDim  = dim3(2048, 1, 1);
    cfg.blockDim = dim3(256, 1, 1);
    cfg.dynamicSmemBytes = 0;
    cfg.stream = 0;
    cudaLaunchAttribute attrs[1];
    attrs[0].id = cudaLaunchAttributeProgrammaticStreamSerialization;
    attrs[0].val.programmaticStreamSerializationAllowed = 1;
    cfg.attrs = attrs;
    cfg.numAttrs = 1;
    cudaLaunchKernelEx(&cfg, outer_product_kernel, out);
}